// round 16
// baseline (speedup 1.0000x reference)
#include <cuda_runtime.h>

#define NPG 23
#define NF 11
#define HID 48
#define C1 192
#define NGRAPH 1024
#define GRUH 64
#define G3 192
#define TT 16
#define BB 64
#define FRAME 96
#define ST 196           // padded float4-aligned stride for 192-wide rows
#define WS 68            // padded float4 stride for 64-wide weight rows
#define AST 24           // padded alpha row stride (23 -> 24, 16B aligned)
#define GSM 11416        // floats of smem per graph

__device__ float g_frames[NGRAPH * FRAME];
__device__ float g_gi0[NGRAPH * G3];

__device__ __forceinline__ float4 ld4(const float* p) { return *(const float4*)p; }
__device__ __forceinline__ float4 ld4g(const float* p) { return __ldg((const float4*)p); }

__device__ __forceinline__ float fast_sigmoid(float x) {
    return __fdividef(1.f, 1.f + __expf(-x));
}
__device__ __forceinline__ float fast_tanh(float x) {
    float e = __expf(-2.f * x);
    return __fdividef(1.f - e, 1.f + e);
}
__device__ __forceinline__ float elu1(float v) {
    return v > 0.f ? v : (__expf(v) - 1.f);
}
__device__ __forceinline__ void fma_row(float4& a, float4 v,
                                        float4 w0, float4 w1, float4 w2, float4 w3) {
    a.x += v.x * w0.x + v.y * w1.x + v.z * w2.x + v.w * w3.x;
    a.y += v.x * w0.y + v.y * w1.y + v.z * w2.y + v.w * w3.y;
    a.z += v.x * w0.z + v.y * w1.z + v.z * w2.z + v.w * w3.z;
    a.w += v.x * w0.w + v.y * w1.w + v.z * w2.w + v.w * w3.w;
}
__device__ __forceinline__ void fma_s(float4& a, float s, float4 h) {
    a.x += s * h.x; a.y += s * h.y; a.z += s * h.z; a.w += s * h.w;
}

// ---------------------------------------------------------------------------
// Kernel 1: fused GAT1 + GAT2 + pooling, TWO graphs per block.
// Each phase runs for graph 0 then graph 1 before the shared barrier:
// barriers per graph halve; 128-reg budget (2 blocks/SM) lets ptxas
// interleave the two independent phase bodies for ILP.
// ---------------------------------------------------------------------------
__global__ void __launch_bounds__(256, 2) gat_kernel(
    const float* __restrict__ x,
    const float* __restrict__ W1,  const float* __restrict__ as1,
    const float* __restrict__ ad1, const float* __restrict__ b1,
    const float* __restrict__ W2,  const float* __restrict__ as2,
    const float* __restrict__ ad2, const float* __restrict__ b2)
{
    extern __shared__ float sm[];
    const int tid = threadIdx.x;
    const int g0  = blockIdx.x * 2;

    // per-graph smem region layout (offsets within S = sm + gg*GSM):
    //   h1     = S          (4508; later h2 partials)
    //   o1     = S + 4508   (4508; later h2|al2|alpha2|o2)
    //   als    = S + 9016   (96)
    //   ald    = S + 9112   (96)
    //   alpha  = S + 9208   (2208)

    // ---- h1 = x @ W1 (both graphs) ----
    #pragma unroll
    for (int gg = 0; gg < 2; gg++) {
        float* h1 = sm + gg * GSM;
        const float* xg = x + (size_t)(g0 + gg) * (NPG * NF);
        if (tid < 240) {
            int c4 = tid % 48, rg = tid / 48;
            int r0 = rg * 5;
            int nr = (r0 + 5 <= NPG) ? 5 : (NPG - r0);
            float4 acc[5];
            #pragma unroll
            for (int rr = 0; rr < 5; rr++) acc[rr] = make_float4(0.f, 0.f, 0.f, 0.f);
            const float* xr = xg + r0 * NF;
            #pragma unroll
            for (int f = 0; f < NF; f++) {
                float4 w = ld4g(W1 + f * C1 + 4 * c4);
                #pragma unroll
                for (int rr = 0; rr < 5; rr++) {
                    if (rr < nr) {
                        float xv = __ldg(xr + rr * NF + f);
                        acc[rr].x += xv * w.x; acc[rr].y += xv * w.y;
                        acc[rr].z += xv * w.z; acc[rr].w += xv * w.w;
                    }
                }
            }
            #pragma unroll
            for (int rr = 0; rr < 5; rr++)
                if (rr < nr) *(float4*)(h1 + (r0 + rr) * ST + 4 * c4) = acc[rr];
        }
    }
    __syncthreads();

    // ---- attention logits (both graphs) ----
    #pragma unroll
    for (int gg = 0; gg < 2; gg++) {
        float* S = sm + gg * GSM;
        float* h1 = S;
        float* als = S + 9016;
        float* ald = S + 9112;
        if (tid < NPG * 4) {
            int i = tid >> 2, hd = tid & 3;
            const float* hrow = h1 + i * ST + hd * HID;
            float ss = 0.f, dd = 0.f;
            #pragma unroll
            for (int k4 = 0; k4 < 12; k4++) {
                float4 v  = ld4(hrow + 4 * k4);
                float4 s4 = ld4g(as1 + hd * HID + 4 * k4);
                float4 d4 = ld4g(ad1 + hd * HID + 4 * k4);
                ss += v.x * s4.x + v.y * s4.y + v.z * s4.z + v.w * s4.w;
                dd += v.x * d4.x + v.y * d4.y + v.z * d4.z + v.w * d4.w;
            }
            als[tid] = ss; ald[tid] = dd;
        }
    }
    __syncthreads();

    // ---- softmax -> alpha (both graphs) ----
    #pragma unroll
    for (int gg = 0; gg < 2; gg++) {
        float* S = sm + gg * GSM;
        float* als = S + 9016;
        float* ald = S + 9112;
        float* alpha = S + 9208;
        if (tid < NPG * 4) {
            int j = tid >> 2, hd = tid & 3;
            float adj = ald[j * 4 + hd];
            float e[NPG];
            float m = -1e30f;
            #pragma unroll
            for (int i = 0; i < NPG; i++) {
                float v = als[i * 4 + hd] + adj;
                v = (v > 0.f) ? v : 0.2f * v;
                e[i] = v; m = fmaxf(m, v);
            }
            float s = 0.f;
            #pragma unroll
            for (int i = 0; i < NPG; i++) { float w = __expf(e[i] - m); e[i] = w; s += w; }
            float inv = __fdividef(1.f, s + 1e-16f);
            float* dst = alpha + (hd * NPG + j) * AST;
            #pragma unroll
            for (int i4 = 0; i4 < 5; i4++)
                *(float4*)(dst + 4 * i4) = make_float4(e[4*i4] * inv, e[4*i4+1] * inv,
                                                       e[4*i4+2] * inv, e[4*i4+3] * inv);
            *(float4*)(dst + 20) = make_float4(e[20] * inv, e[21] * inv, e[22] * inv, 0.f);
        }
    }
    __syncthreads();

    // ---- aggregate1 + bias + elu -> o1 (both graphs) ----
    #pragma unroll
    for (int gg = 0; gg < 2; gg++) {
        float* S = sm + gg * GSM;
        float* h1 = S;
        float* o1 = S + 4508;
        float* alpha = S + 9208;
        if (tid < 240) {
            int c4 = tid % 48, rg = tid / 48;
            int j0 = rg * 5;
            int nj = (j0 + 5 <= NPG) ? 5 : (NPG - j0);
            int hd = c4 / 12;
            float4 bv = ld4g(b1 + 4 * c4);
            float4 acc[5];
            #pragma unroll
            for (int jj = 0; jj < 5; jj++) acc[jj] = bv;
            const float* arow = alpha + (hd * NPG + j0) * AST;
            #pragma unroll
            for (int i4 = 0; i4 < 6; i4++) {
                float4 hv[4];
                #pragma unroll
                for (int r = 0; r < 4; r++) {
                    int i = 4 * i4 + r;
                    if (i < NPG) hv[r] = ld4(h1 + i * ST + 4 * c4);
                }
                #pragma unroll
                for (int jj = 0; jj < 5; jj++) {
                    if (jj < nj) {
                        float4 a4 = ld4(arow + jj * AST + 4 * i4);
                        if (4 * i4 + 0 < NPG) fma_s(acc[jj], a4.x, hv[0]);
                        if (4 * i4 + 1 < NPG) fma_s(acc[jj], a4.y, hv[1]);
                        if (4 * i4 + 2 < NPG) fma_s(acc[jj], a4.z, hv[2]);
                        if (4 * i4 + 3 < NPG) fma_s(acc[jj], a4.w, hv[3]);
                    }
                }
            }
            #pragma unroll
            for (int jj = 0; jj < 5; jj++) {
                if (jj < nj) {
                    float4 a = acc[jj];
                    a.x = elu1(a.x); a.y = elu1(a.y); a.z = elu1(a.z); a.w = elu1(a.w);
                    *(float4*)(o1 + (j0 + jj) * ST + 4 * c4) = a;
                }
            }
        }
    }
    __syncthreads();

    // ---- h2 = o1 @ W2 (K-split partials, both graphs) ----
    #pragma unroll
    for (int gg = 0; gg < 2; gg++) {
        float* S = sm + gg * GSM;
        float* part = S;          // aliases h1
        float* o1 = S + 4508;
        if (tid < 192) {
            int k4 = tid % 12;
            int rg = (tid / 12) % 8;
            int ks = tid / 96;
            int r0 = rg * 3;
            int nr = (r0 + 3 <= NPG) ? 3 : (NPG - r0);
            int r1 = (r0 + 1 < NPG) ? r0 + 1 : NPG - 1;
            int r2 = (r0 + 2 < NPG) ? r0 + 2 : NPG - 1;
            int c0 = ks * 96;
            float4 a0 = make_float4(0.f,0.f,0.f,0.f);
            float4 a1 = a0, a2 = a0;
            const float* p0 = o1 + r0 * ST;
            const float* p1 = o1 + r1 * ST;
            const float* p2 = o1 + r2 * ST;
            #pragma unroll 6
            for (int c4i = 0; c4i < 24; c4i++) {
                int c = c0 + 4 * c4i;
                float4 v0 = ld4(p0 + c);
                float4 v1 = ld4(p1 + c);
                float4 v2 = ld4(p2 + c);
                const float* wp = W2 + c * HID + 4 * k4;
                float4 w0 = ld4g(wp);
                float4 w1 = ld4g(wp + HID);
                float4 w2 = ld4g(wp + 2 * HID);
                float4 w3 = ld4g(wp + 3 * HID);
                fma_row(a0, v0, w0, w1, w2, w3);
                fma_row(a1, v1, w0, w1, w2, w3);
                fma_row(a2, v2, w0, w1, w2, w3);
            }
            float* dst = part + ks * 1104 + r0 * 48 + 4 * k4;
            *(float4*)(dst) = a0;
            if (nr > 1) *(float4*)(dst + 48) = a1;
            if (nr > 2) *(float4*)(dst + 96) = a2;
        }
    }
    __syncthreads();

    // ---- combine partials -> h2 (both graphs) ----
    #pragma unroll
    for (int gg = 0; gg < 2; gg++) {
        float* S = sm + gg * GSM;
        float* part = S;
        float* h2 = S + 4508;     // aliases o1 base
        for (int i4 = tid; i4 < 276; i4 += 256) {
            float4 q0 = ((const float4*)part)[i4];
            float4 q1 = ((const float4*)(part + 1104))[i4];
            float4 s;
            s.x = q0.x + q1.x; s.y = q0.y + q1.y;
            s.z = q0.z + q1.z; s.w = q0.w + q1.w;
            ((float4*)h2)[i4] = s;
        }
    }
    __syncthreads();

    // ---- GAT2 logits (both graphs) ----
    #pragma unroll
    for (int gg = 0; gg < 2; gg++) {
        float* S = sm + gg * GSM;
        float* h2 = S + 4508;
        float* al2s = S + 4508 + 1104;
        float* al2d = S + 4508 + 1128;
        if (tid < NPG) {
            const float* hrow = h2 + tid * HID;
            float ss = 0.f, dd = 0.f;
            #pragma unroll
            for (int k4 = 0; k4 < 12; k4++) {
                float4 v  = ld4(hrow + 4 * k4);
                float4 s4 = ld4g(as2 + 4 * k4);
                float4 d4 = ld4g(ad2 + 4 * k4);
                ss += v.x * s4.x + v.y * s4.y + v.z * s4.z + v.w * s4.w;
                dd += v.x * d4.x + v.y * d4.y + v.z * d4.z + v.w * d4.w;
            }
            al2s[tid] = ss; al2d[tid] = dd;
        }
    }
    __syncthreads();

    // ---- GAT2 softmax -> alpha2 (both graphs) ----
    #pragma unroll
    for (int gg = 0; gg < 2; gg++) {
        float* S = sm + gg * GSM;
        float* al2s = S + 4508 + 1104;
        float* al2d = S + 4508 + 1128;
        float* alpha2 = S + 4508 + 1152;
        if (tid < NPG) {
            int j = tid;
            float adj = al2d[j];
            float e[NPG];
            float m = -1e30f;
            #pragma unroll
            for (int i = 0; i < NPG; i++) {
                float v = al2s[i] + adj;
                v = (v > 0.f) ? v : 0.2f * v;
                e[i] = v; m = fmaxf(m, v);
            }
            float s = 0.f;
            #pragma unroll
            for (int i = 0; i < NPG; i++) { float w = __expf(e[i] - m); e[i] = w; s += w; }
            float inv = __fdividef(1.f, s + 1e-16f);
            float* dst = alpha2 + j * AST;
            #pragma unroll
            for (int i4 = 0; i4 < 5; i4++)
                *(float4*)(dst + 4 * i4) = make_float4(e[4*i4] * inv, e[4*i4+1] * inv,
                                                       e[4*i4+2] * inv, e[4*i4+3] * inv);
            *(float4*)(dst + 20) = make_float4(e[20] * inv, e[21] * inv, e[22] * inv, 0.f);
        }
    }
    __syncthreads();

    // ---- aggregate2 + bias + elu -> o2 (both graphs) ----
    #pragma unroll
    for (int gg = 0; gg < 2; gg++) {
        float* S = sm + gg * GSM;
        float* h2 = S + 4508;
        float* alpha2 = S + 4508 + 1152;
        float* o2 = S + 4508 + 1704;
        if (tid < 144) {
            int k4 = tid % 12, rg = tid / 12;
            int j0 = rg * 2;
            int nj = (j0 + 2 <= NPG) ? 2 : (NPG - j0);
            float4 bv = ld4g(b2 + 4 * k4);
            float4 acc[2];
            acc[0] = bv; acc[1] = bv;
            const float* arow = alpha2 + j0 * AST;
            #pragma unroll
            for (int i4 = 0; i4 < 6; i4++) {
                float4 hv[4];
                #pragma unroll
                for (int r = 0; r < 4; r++) {
                    int i = 4 * i4 + r;
                    if (i < NPG) hv[r] = ld4(h2 + i * HID + 4 * k4);
                }
                #pragma unroll
                for (int jj = 0; jj < 2; jj++) {
                    if (jj < nj) {
                        float4 a4 = ld4(arow + jj * AST + 4 * i4);
                        if (4 * i4 + 0 < NPG) fma_s(acc[jj], a4.x, hv[0]);
                        if (4 * i4 + 1 < NPG) fma_s(acc[jj], a4.y, hv[1]);
                        if (4 * i4 + 2 < NPG) fma_s(acc[jj], a4.z, hv[2]);
                        if (4 * i4 + 3 < NPG) fma_s(acc[jj], a4.w, hv[3]);
                    }
                }
            }
            #pragma unroll
            for (int jj = 0; jj < 2; jj++) {
                if (jj < nj) {
                    float4 a = acc[jj];
                    a.x = elu1(a.x); a.y = elu1(a.y); a.z = elu1(a.z); a.w = elu1(a.w);
                    *(float4*)(o2 + (j0 + jj) * HID + 4 * k4) = a;
                }
            }
        }
    }
    __syncthreads();

    // ---- mean/max pooling (both graphs) ----
    #pragma unroll
    for (int gg = 0; gg < 2; gg++) {
        float* S = sm + gg * GSM;
        float* o2 = S + 4508 + 1704;
        if (tid < HID) {
            float s = 0.f, m = -1e30f;
            #pragma unroll
            for (int j = 0; j < NPG; j++) {
                float v = o2[j * HID + tid];
                s += v; m = fmaxf(m, v);
            }
            g_frames[(size_t)(g0 + gg) * FRAME + tid]       = s * (1.f / (float)NPG);
            g_frames[(size_t)(g0 + gg) * FRAME + HID + tid] = m;
        }
    }
}

// ---------------------------------------------------------------------------
// Kernel 2: gi0 = frames @ Wih0^T + bih0 (proven wide GEMM).
// ---------------------------------------------------------------------------
#define GI0_GPB 8
__global__ void __launch_bounds__(192) gi0_kernel(const float* __restrict__ Wih0,
                                                  const float* __restrict__ bih0)
{
    extern __shared__ float smem[];
    float* W  = smem;
    float* xf = smem + G3 * 100;

    const int tid = threadIdx.x;
    const int b0  = blockIdx.x * GI0_GPB;

    for (int i4 = tid; i4 < G3 * 24; i4 += 192) {
        int r = i4 / 24, c4 = i4 - (i4 / 24) * 24;
        *(float4*)(W + r * 100 + 4 * c4) = ld4(Wih0 + r * 96 + 4 * c4);
    }
    for (int i4 = tid; i4 < GI0_GPB * 24; i4 += 192)
        ((float4*)xf)[i4] = ((const float4*)(g_frames + (size_t)b0 * FRAME))[i4];
    __syncthreads();

    const int r = tid;
    float acc[GI0_GPB];
    float bi = bih0[r];
    #pragma unroll
    for (int gg = 0; gg < GI0_GPB; gg++) acc[gg] = bi;
    const float4* wr = (const float4*)(W + r * 100);
    #pragma unroll
    for (int f4 = 0; f4 < 24; f4++) {
        float4 w = wr[f4];
        #pragma unroll
        for (int gg = 0; gg < GI0_GPB; gg++) {
            float4 xv = ld4(xf + gg * 96 + 4 * f4);
            acc[gg] += w.x * xv.x + w.y * xv.y + w.z * xv.z + w.w * xv.w;
        }
    }
    #pragma unroll
    for (int gg = 0; gg < GI0_GPB; gg++)
        g_gi0[(size_t)(b0 + gg) * G3 + r] = acc[gg];
}

// ---------------------------------------------------------------------------
// Kernel 3: 2-layer GRU + MLP head (proven half-split structure).
// ---------------------------------------------------------------------------
__global__ void __launch_bounds__(384) gru_kernel(
    const float* __restrict__ Whh0, const float* __restrict__ bhh0,
    const float* __restrict__ Wih1, const float* __restrict__ bih1,
    const float* __restrict__ Whh1, const float* __restrict__ bhh1,
    const float* __restrict__ Wh1,  const float* __restrict__ bh1,
    const float* __restrict__ Wh2,  const float* __restrict__ bh2,
    float* __restrict__ out)
{
    extern __shared__ float smem[];
    float* Whs0 = smem;
    float* Whs1 = Whs0 + G3 * WS;
    float* Wis1 = Whs1 + G3 * WS;
    float* gi   = Wis1 + G3 * WS;
    float* seq  = gi + TT * G3;
    float* hbuf = seq + TT * GRUH;
    float* ghp  = hbuf + GRUH;
    float* q    = ghp + 2 * G3;

    const int b    = blockIdx.x;
    const int tid  = threadIdx.x;
    const int row  = tid % G3;
    const int half = tid / G3;

    for (int i4 = tid; i4 < TT * G3 / 4; i4 += 384)
        ((float4*)gi)[i4] = ((const float4*)(g_gi0 + (size_t)b * TT * G3))[i4];
    for (int i4 = tid; i4 < G3 * 16; i4 += 384) {
        int r = i4 >> 4, c4 = i4 & 15;
        *(float4*)(Whs0 + r * WS + 4 * c4) = ld4g(Whh0 + r * GRUH + 4 * c4);
        *(float4*)(Whs1 + r * WS + 4 * c4) = ld4g(Whh1 + r * GRUH + 4 * c4);
        *(float4*)(Wis1 + r * WS + 4 * c4) = ld4g(Wih1 + r * GRUH + 4 * c4);
    }
    if (tid < GRUH) hbuf[tid] = 0.f;
    __syncthreads();

    float wr[32];
    {
        const float* wrow = Whs0 + row * WS + half * 32;
        #pragma unroll
        for (int i = 0; i < 8; i++) {
            float4 v = ld4(wrow + 4 * i);
            wr[4*i] = v.x; wr[4*i+1] = v.y; wr[4*i+2] = v.z; wr[4*i+3] = v.w;
        }
    }
    float bh = (half == 0) ? __ldg(bhh0 + row) : 0.f;
    __syncthreads();

    for (int t = 0; t < TT; t++) {
        const float* hb = hbuf + half * 32;
        float acc[4] = {0.f, 0.f, 0.f, 0.f};
        #pragma unroll
        for (int j = 0; j < 4; j++) {
            float4 ha = ld4(hb + 8 * j);
            float4 hc = ld4(hb + 8 * j + 4);
            acc[j] += wr[8*j  ]*ha.x + wr[8*j+1]*ha.y + wr[8*j+2]*ha.z + wr[8*j+3]*ha.w
                    + wr[8*j+4]*hc.x + wr[8*j+5]*hc.y + wr[8*j+6]*hc.z + wr[8*j+7]*hc.w;
        }
        ghp[half * G3 + row] = (acc[0] + acc[1]) + (acc[2] + acc[3]) + bh;
        __syncthreads();
        if (tid < GRUH) {
            float ghr = ghp[tid]       + ghp[G3 + tid];
            float ghz = ghp[64 + tid]  + ghp[G3 + 64 + tid];
            float ghn = ghp[128 + tid] + ghp[G3 + 128 + tid];
            float r = fast_sigmoid(gi[t * G3 + tid] + ghr);
            float z = fast_sigmoid(gi[t * G3 + GRUH + tid] + ghz);
            float n = fast_tanh(gi[t * G3 + 2 * GRUH + tid] + r * ghn);
            float hn = (1.f - z) * n + z * hbuf[tid];
            hbuf[tid] = hn;
            seq[t * GRUH + tid] = hn;
        }
        __syncthreads();
    }

    {
        float acc8[8];
        float bi = __ldg(bih1 + row);
        #pragma unroll
        for (int t = 0; t < 8; t++) acc8[t] = bi;
        const float* wrow = Wis1 + row * WS;
        const int t0 = half * 8;
        #pragma unroll
        for (int f4 = 0; f4 < 16; f4++) {
            float4 w = ld4(wrow + 4 * f4);
            #pragma unroll
            for (int t = 0; t < 8; t++) {
                float4 xv = ld4(seq + (t0 + t) * GRUH + 4 * f4);
                acc8[t] += w.x * xv.x + w.y * xv.y + w.z * xv.z + w.w * xv.w;
            }
        }
        #pragma unroll
        for (int t = 0; t < 8; t++) gi[(t0 + t) * G3 + row] = acc8[t];
    }

    {
        const float* wrow = Whs1 + row * WS + half * 32;
        #pragma unroll
        for (int i = 0; i < 8; i++) {
            float4 v = ld4(wrow + 4 * i);
            wr[4*i] = v.x; wr[4*i+1] = v.y; wr[4*i+2] = v.z; wr[4*i+3] = v.w;
        }
    }
    bh = (half == 0) ? __ldg(bhh1 + row) : 0.f;
    if (tid < GRUH) hbuf[tid] = 0.f;
    __syncthreads();

    for (int t = 0; t < TT; t++) {
        const float* hb = hbuf + half * 32;
        float acc[4] = {0.f, 0.f, 0.f, 0.f};
        #pragma unroll
        for (int j = 0; j < 4; j++) {
            float4 ha = ld4(hb + 8 * j);
            float4 hc = ld4(hb + 8 * j + 4);
            acc[j] += wr[8*j  ]*ha.x + wr[8*j+1]*ha.y + wr[8*j+2]*ha.z + wr[8*j+3]*ha.w
                    + wr[8*j+4]*hc.x + wr[8*j+5]*hc.y + wr[8*j+6]*hc.z + wr[8*j+7]*hc.w;
        }
        ghp[half * G3 + row] = (acc[0] + acc[1]) + (acc[2] + acc[3]) + bh;
        __syncthreads();
        if (tid < GRUH) {
            float ghr = ghp[tid]       + ghp[G3 + tid];
            float ghz = ghp[64 + tid]  + ghp[G3 + 64 + tid];
            float ghn = ghp[128 + tid] + ghp[G3 + 128 + tid];
            float r = fast_sigmoid(gi[t * G3 + tid] + ghr);
            float z = fast_sigmoid(gi[t * G3 + GRUH + tid] + ghz);
            float n = fast_tanh(gi[t * G3 + 2 * GRUH + tid] + r * ghn);
            hbuf[tid] = (1.f - z) * n + z * hbuf[tid];
        }
        __syncthreads();
    }

    if (tid < 32) {
        float acc = __ldg(bh1 + tid);
        #pragma unroll
        for (int u = 0; u < GRUH; u++) acc += hbuf[u] * __ldg(Wh1 + u * 32 + tid);
        q[tid] = fmaxf(acc, 0.f);
    }
    __syncthreads();
    if (tid == 0) {
        float acc = __ldg(bh2);
        #pragma unroll
        for (int m = 0; m < 32; m++) acc += q[m] * __ldg(Wh2 + m);
        out[b] = acc;
    }
}

// ---------------------------------------------------------------------------
extern "C" void kernel_launch(void* const* d_in, const int* in_sizes, int n_in,
                              void* d_out, int out_size)
{
    const float* x    = (const float*)d_in[0];
    const float* W1   = (const float*)d_in[3];
    const float* as1  = (const float*)d_in[4];
    const float* ad1  = (const float*)d_in[5];
    const float* b1   = (const float*)d_in[6];
    const float* W2   = (const float*)d_in[7];
    const float* as2  = (const float*)d_in[8];
    const float* ad2  = (const float*)d_in[9];
    const float* b2   = (const float*)d_in[10];
    const float* Wih0 = (const float*)d_in[11];
    const float* Whh0 = (const float*)d_in[12];
    const float* bih0 = (const float*)d_in[13];
    const float* bhh0 = (const float*)d_in[14];
    const float* Wih1 = (const float*)d_in[15];
    const float* Whh1 = (const float*)d_in[16];
    const float* bih1 = (const float*)d_in[17];
    const float* bhh1 = (const float*)d_in[18];
    const float* Wh1  = (const float*)d_in[19];
    const float* bh1  = (const float*)d_in[20];
    const float* Wh2  = (const float*)d_in[21];
    const float* bh2  = (const float*)d_in[22];

    const int GAT_SMEM = 2 * GSM * 4;   // 91328 B -> 2 blocks/SM
    const int GI0_SMEM = (G3 * 100 + GI0_GPB * FRAME) * 4;
    const int GRU_SMEM = 43744 * 4;

    static bool attrs_set = false;
    if (!attrs_set) {
        cudaFuncSetAttribute(gat_kernel, cudaFuncAttributeMaxDynamicSharedMemorySize, GAT_SMEM);
        cudaFuncSetAttribute(gi0_kernel, cudaFuncAttributeMaxDynamicSharedMemorySize, GI0_SMEM);
        cudaFuncSetAttribute(gru_kernel, cudaFuncAttributeMaxDynamicSharedMemorySize, GRU_SMEM);
        attrs_set = true;
    }

    gat_kernel<<<NGRAPH / 2, 256, GAT_SMEM>>>(x, W1, as1, ad1, b1, W2, as2, ad2, b2);
    gi0_kernel<<<NGRAPH / GI0_GPB, 192, GI0_SMEM>>>(Wih0, bih0);
    gru_kernel<<<BB, 384, GRU_SMEM>>>(Whh0, bhh0, Wih1, bih1, Whh1, bhh1,
                                      Wh1, bh1, Wh2, bh2, (float*)d_out);
}

// round 17
// speedup vs baseline: 1.0728x; 1.0728x over previous
#include <cuda_runtime.h>

#define NPG 23
#define NF 11
#define HID 48
#define C1 192
#define NGRAPH 1024
#define GRUH 64
#define G3 192
#define TT 16
#define BB 64
#define FRAME 96
#define ST 196           // padded float4-aligned stride for 192-wide rows
#define WS 68            // padded float4 stride for 64-wide weight rows
#define AST 24           // padded alpha row stride (23 -> 24, 16B aligned)

__device__ float g_frames[NGRAPH * FRAME];
__device__ float g_gi0[NGRAPH * G3];

__device__ __forceinline__ float4 ld4(const float* p) { return *(const float4*)p; }
__device__ __forceinline__ float4 ld4g(const float* p) { return __ldg((const float4*)p); }

__device__ __forceinline__ float fast_sigmoid(float x) {
    return __fdividef(1.f, 1.f + __expf(-x));
}
__device__ __forceinline__ float fast_tanh(float x) {
    float e = __expf(-2.f * x);
    return __fdividef(1.f - e, 1.f + e);
}
__device__ __forceinline__ float elu1(float v) {
    return v > 0.f ? v : (__expf(v) - 1.f);
}
__device__ __forceinline__ void fma_row(float4& a, float4 v,
                                        float4 w0, float4 w1, float4 w2, float4 w3) {
    a.x += v.x * w0.x + v.y * w1.x + v.z * w2.x + v.w * w3.x;
    a.y += v.x * w0.y + v.y * w1.y + v.z * w2.y + v.w * w3.y;
    a.z += v.x * w0.z + v.y * w1.z + v.z * w2.z + v.w * w3.z;
    a.w += v.x * w0.w + v.y * w1.w + v.z * w2.w + v.w * w3.w;
}
__device__ __forceinline__ void fma_s(float4& a, float s, float4 h) {
    a.x += s * h.x; a.y += s * h.y; a.z += s * h.z; a.w += s * h.w;
}

// ---------------------------------------------------------------------------
// Kernel 1: fused GAT1 + GAT2 + pooling (proven 71.7 configuration:
// 256 thr, 4 blocks/SM, 64 regs; weights streamed from L2; alpha stride 24).
// ---------------------------------------------------------------------------
__global__ void __launch_bounds__(256, 4) gat_kernel(
    const float* __restrict__ x,
    const float* __restrict__ W1,  const float* __restrict__ as1,
    const float* __restrict__ ad1, const float* __restrict__ b1,
    const float* __restrict__ W2,  const float* __restrict__ as2,
    const float* __restrict__ ad2, const float* __restrict__ b2)
{
    extern __shared__ float sm[];
    float* h1    = sm;              // 4508 ; later h2 partials
    float* o1    = h1 + 4508;       // 4508 ; later h2|al2|alpha2|o2
    float* als   = o1 + 4508;       // 96
    float* ald   = als + 96;        // 96
    float* alpha = ald + 96;        // 4*23*24 = 2208
    float* h2     = o1;
    float* al2s   = o1 + 1104;
    float* al2d   = o1 + 1128;
    float* alpha2 = o1 + 1152;
    float* o2     = o1 + 1704;

    const int tid = threadIdx.x;
    const int g   = blockIdx.x;
    const float* xg = x + (size_t)g * (NPG * NF);

    // ---- h1 = x @ W1 : x read via broadcast __ldg ----
    if (tid < 240) {
        int c4 = tid % 48, rg = tid / 48;
        int r0 = rg * 5;
        int nr = (r0 + 5 <= NPG) ? 5 : (NPG - r0);
        float4 acc[5];
        #pragma unroll
        for (int rr = 0; rr < 5; rr++) acc[rr] = make_float4(0.f, 0.f, 0.f, 0.f);
        const float* xr = xg + r0 * NF;
        #pragma unroll
        for (int f = 0; f < NF; f++) {
            float4 w = ld4g(W1 + f * C1 + 4 * c4);
            #pragma unroll
            for (int rr = 0; rr < 5; rr++) {
                if (rr < nr) {
                    float xv = __ldg(xr + rr * NF + f);
                    acc[rr].x += xv * w.x; acc[rr].y += xv * w.y;
                    acc[rr].z += xv * w.z; acc[rr].w += xv * w.w;
                }
            }
        }
        #pragma unroll
        for (int rr = 0; rr < 5; rr++)
            if (rr < nr) *(float4*)(h1 + (r0 + rr) * ST + 4 * c4) = acc[rr];
    }
    __syncthreads();

    // ---- attention logits ----
    if (tid < NPG * 4) {
        int i = tid >> 2, hd = tid & 3;
        const float* hrow = h1 + i * ST + hd * HID;
        float ss = 0.f, dd = 0.f;
        #pragma unroll
        for (int k4 = 0; k4 < 12; k4++) {
            float4 v  = ld4(hrow + 4 * k4);
            float4 s4 = ld4g(as1 + hd * HID + 4 * k4);
            float4 d4 = ld4g(ad1 + hd * HID + 4 * k4);
            ss += v.x * s4.x + v.y * s4.y + v.z * s4.z + v.w * s4.w;
            dd += v.x * d4.x + v.y * d4.y + v.z * d4.z + v.w * d4.w;
        }
        als[tid] = ss; ald[tid] = dd;
    }
    __syncthreads();

    // ---- softmax -> alpha (stride 24, float4 stores, zero-padded) ----
    if (tid < NPG * 4) {
        int j = tid >> 2, hd = tid & 3;
        float adj = ald[j * 4 + hd];
        float e[NPG];
        float m = -1e30f;
        #pragma unroll
        for (int i = 0; i < NPG; i++) {
            float v = als[i * 4 + hd] + adj;
            v = (v > 0.f) ? v : 0.2f * v;
            e[i] = v; m = fmaxf(m, v);
        }
        float s = 0.f;
        #pragma unroll
        for (int i = 0; i < NPG; i++) { float w = __expf(e[i] - m); e[i] = w; s += w; }
        float inv = __fdividef(1.f, s + 1e-16f);
        float* dst = alpha + (hd * NPG + j) * AST;
        #pragma unroll
        for (int i4 = 0; i4 < 5; i4++)
            *(float4*)(dst + 4 * i4) = make_float4(e[4*i4] * inv, e[4*i4+1] * inv,
                                                   e[4*i4+2] * inv, e[4*i4+3] * inv);
        *(float4*)(dst + 20) = make_float4(e[20] * inv, e[21] * inv, e[22] * inv, 0.f);
    }
    __syncthreads();

    // ---- aggregate1 + bias + elu -> o1 (vectorized alpha reads) ----
    if (tid < 240) {
        int c4 = tid % 48, rg = tid / 48;
        int j0 = rg * 5;
        int nj = (j0 + 5 <= NPG) ? 5 : (NPG - j0);
        int hd = c4 / 12;
        float4 bv = ld4g(b1 + 4 * c4);
        float4 acc[5];
        #pragma unroll
        for (int jj = 0; jj < 5; jj++) acc[jj] = bv;
        const float* arow = alpha + (hd * NPG + j0) * AST;
        #pragma unroll
        for (int i4 = 0; i4 < 6; i4++) {
            float4 hv[4];
            #pragma unroll
            for (int r = 0; r < 4; r++) {
                int i = 4 * i4 + r;
                if (i < NPG) hv[r] = ld4(h1 + i * ST + 4 * c4);
            }
            #pragma unroll
            for (int jj = 0; jj < 5; jj++) {
                if (jj < nj) {
                    float4 a4 = ld4(arow + jj * AST + 4 * i4);
                    if (4 * i4 + 0 < NPG) fma_s(acc[jj], a4.x, hv[0]);
                    if (4 * i4 + 1 < NPG) fma_s(acc[jj], a4.y, hv[1]);
                    if (4 * i4 + 2 < NPG) fma_s(acc[jj], a4.z, hv[2]);
                    if (4 * i4 + 3 < NPG) fma_s(acc[jj], a4.w, hv[3]);
                }
            }
        }
        #pragma unroll
        for (int jj = 0; jj < 5; jj++) {
            if (jj < nj) {
                float4 a = acc[jj];
                a.x = elu1(a.x); a.y = elu1(a.y); a.z = elu1(a.z); a.w = elu1(a.w);
                *(float4*)(o1 + (j0 + jj) * ST + 4 * c4) = a;
            }
        }
    }
    __syncthreads();

    // ---- h2 = o1 @ W2 (K-split partials) ----
    {
        float* part = h1;
        if (tid < 192) {
            int k4 = tid % 12;
            int rg = (tid / 12) % 8;
            int ks = tid / 96;
            int r0 = rg * 3;
            int nr = (r0 + 3 <= NPG) ? 3 : (NPG - r0);
            int r1 = (r0 + 1 < NPG) ? r0 + 1 : NPG - 1;
            int r2 = (r0 + 2 < NPG) ? r0 + 2 : NPG - 1;
            int c0 = ks * 96;
            float4 a0 = make_float4(0.f,0.f,0.f,0.f);
            float4 a1 = a0, a2 = a0;
            const float* p0 = o1 + r0 * ST;
            const float* p1 = o1 + r1 * ST;
            const float* p2 = o1 + r2 * ST;
            #pragma unroll 6
            for (int c4i = 0; c4i < 24; c4i++) {
                int c = c0 + 4 * c4i;
                float4 v0 = ld4(p0 + c);
                float4 v1 = ld4(p1 + c);
                float4 v2 = ld4(p2 + c);
                const float* wp = W2 + c * HID + 4 * k4;
                float4 w0 = ld4g(wp);
                float4 w1 = ld4g(wp + HID);
                float4 w2 = ld4g(wp + 2 * HID);
                float4 w3 = ld4g(wp + 3 * HID);
                fma_row(a0, v0, w0, w1, w2, w3);
                fma_row(a1, v1, w0, w1, w2, w3);
                fma_row(a2, v2, w0, w1, w2, w3);
            }
            float* dst = part + ks * 1104 + r0 * 48 + 4 * k4;
            *(float4*)(dst) = a0;
            if (nr > 1) *(float4*)(dst + 48) = a1;
            if (nr > 2) *(float4*)(dst + 96) = a2;
        }
        __syncthreads();
        for (int i4 = tid; i4 < 276; i4 += 256) {
            float4 q0 = ((const float4*)part)[i4];
            float4 q1 = ((const float4*)(part + 1104))[i4];
            float4 s;
            s.x = q0.x + q1.x; s.y = q0.y + q1.y;
            s.z = q0.z + q1.z; s.w = q0.w + q1.w;
            ((float4*)h2)[i4] = s;
        }
    }
    __syncthreads();

    // ---- GAT2 logits ----
    if (tid < NPG) {
        const float* hrow = h2 + tid * HID;
        float ss = 0.f, dd = 0.f;
        #pragma unroll
        for (int k4 = 0; k4 < 12; k4++) {
            float4 v  = ld4(hrow + 4 * k4);
            float4 s4 = ld4g(as2 + 4 * k4);
            float4 d4 = ld4g(ad2 + 4 * k4);
            ss += v.x * s4.x + v.y * s4.y + v.z * s4.z + v.w * s4.w;
            dd += v.x * d4.x + v.y * d4.y + v.z * d4.z + v.w * d4.w;
        }
        al2s[tid] = ss; al2d[tid] = dd;
    }
    __syncthreads();

    if (tid < NPG) {
        int j = tid;
        float adj = al2d[j];
        float e[NPG];
        float m = -1e30f;
        #pragma unroll
        for (int i = 0; i < NPG; i++) {
            float v = al2s[i] + adj;
            v = (v > 0.f) ? v : 0.2f * v;
            e[i] = v; m = fmaxf(m, v);
        }
        float s = 0.f;
        #pragma unroll
        for (int i = 0; i < NPG; i++) { float w = __expf(e[i] - m); e[i] = w; s += w; }
        float inv = __fdividef(1.f, s + 1e-16f);
        float* dst = alpha2 + j * AST;
        #pragma unroll
        for (int i4 = 0; i4 < 5; i4++)
            *(float4*)(dst + 4 * i4) = make_float4(e[4*i4] * inv, e[4*i4+1] * inv,
                                                   e[4*i4+2] * inv, e[4*i4+3] * inv);
        *(float4*)(dst + 20) = make_float4(e[20] * inv, e[21] * inv, e[22] * inv, 0.f);
    }
    __syncthreads();

    // ---- aggregate2 + bias + elu -> o2 (vectorized alpha2 reads) ----
    if (tid < 144) {
        int k4 = tid % 12, rg = tid / 12;
        int j0 = rg * 2;
        int nj = (j0 + 2 <= NPG) ? 2 : (NPG - j0);
        float4 bv = ld4g(b2 + 4 * k4);
        float4 acc[2];
        acc[0] = bv; acc[1] = bv;
        const float* arow = alpha2 + j0 * AST;
        #pragma unroll
        for (int i4 = 0; i4 < 6; i4++) {
            float4 hv[4];
            #pragma unroll
            for (int r = 0; r < 4; r++) {
                int i = 4 * i4 + r;
                if (i < NPG) hv[r] = ld4(h2 + i * HID + 4 * k4);
            }
            #pragma unroll
            for (int jj = 0; jj < 2; jj++) {
                if (jj < nj) {
                    float4 a4 = ld4(arow + jj * AST + 4 * i4);
                    if (4 * i4 + 0 < NPG) fma_s(acc[jj], a4.x, hv[0]);
                    if (4 * i4 + 1 < NPG) fma_s(acc[jj], a4.y, hv[1]);
                    if (4 * i4 + 2 < NPG) fma_s(acc[jj], a4.z, hv[2]);
                    if (4 * i4 + 3 < NPG) fma_s(acc[jj], a4.w, hv[3]);
                }
            }
        }
        #pragma unroll
        for (int jj = 0; jj < 2; jj++) {
            if (jj < nj) {
                float4 a = acc[jj];
                a.x = elu1(a.x); a.y = elu1(a.y); a.z = elu1(a.z); a.w = elu1(a.w);
                *(float4*)(o2 + (j0 + jj) * HID + 4 * k4) = a;
            }
        }
    }
    __syncthreads();

    if (tid < HID) {
        float s = 0.f, m = -1e30f;
        #pragma unroll
        for (int j = 0; j < NPG; j++) {
            float v = o2[j * HID + tid];
            s += v; m = fmaxf(m, v);
        }
        g_frames[g * FRAME + tid]       = s * (1.f / (float)NPG);
        g_frames[g * FRAME + HID + tid] = m;
    }
}

// ---------------------------------------------------------------------------
// Kernel 2: gi0 = frames @ Wih0^T + bih0 (proven wide GEMM).
// ---------------------------------------------------------------------------
#define GI0_GPB 8
__global__ void __launch_bounds__(192) gi0_kernel(const float* __restrict__ Wih0,
                                                  const float* __restrict__ bih0)
{
    extern __shared__ float smem[];
    float* W  = smem;
    float* xf = smem + G3 * 100;

    const int tid = threadIdx.x;
    const int b0  = blockIdx.x * GI0_GPB;

    for (int i4 = tid; i4 < G3 * 24; i4 += 192) {
        int r = i4 / 24, c4 = i4 - (i4 / 24) * 24;
        *(float4*)(W + r * 100 + 4 * c4) = ld4(Wih0 + r * 96 + 4 * c4);
    }
    for (int i4 = tid; i4 < GI0_GPB * 24; i4 += 192)
        ((float4*)xf)[i4] = ((const float4*)(g_frames + (size_t)b0 * FRAME))[i4];
    __syncthreads();

    const int r = tid;
    float acc[GI0_GPB];
    float bi = bih0[r];
    #pragma unroll
    for (int gg = 0; gg < GI0_GPB; gg++) acc[gg] = bi;
    const float4* wr = (const float4*)(W + r * 100);
    #pragma unroll
    for (int f4 = 0; f4 < 24; f4++) {
        float4 w = wr[f4];
        #pragma unroll
        for (int gg = 0; gg < GI0_GPB; gg++) {
            float4 xv = ld4(xf + gg * 96 + 4 * f4);
            acc[gg] += w.x * xv.x + w.y * xv.y + w.z * xv.z + w.w * xv.w;
        }
    }
    #pragma unroll
    for (int gg = 0; gg < GI0_GPB; gg++)
        g_gi0[(size_t)(b0 + gg) * G3 + r] = acc[gg];
}

// ---------------------------------------------------------------------------
// Kernel 3: 2-layer GRU + MLP head (proven half-split structure).
// ---------------------------------------------------------------------------
__global__ void __launch_bounds__(384) gru_kernel(
    const float* __restrict__ Whh0, const float* __restrict__ bhh0,
    const float* __restrict__ Wih1, const float* __restrict__ bih1,
    const float* __restrict__ Whh1, const float* __restrict__ bhh1,
    const float* __restrict__ Wh1,  const float* __restrict__ bh1,
    const float* __restrict__ Wh2,  const float* __restrict__ bh2,
    float* __restrict__ out)
{
    extern __shared__ float smem[];
    float* Whs0 = smem;
    float* Whs1 = Whs0 + G3 * WS;
    float* Wis1 = Whs1 + G3 * WS;
    float* gi   = Wis1 + G3 * WS;
    float* seq  = gi + TT * G3;
    float* hbuf = seq + TT * GRUH;
    float* ghp  = hbuf + GRUH;
    float* q    = ghp + 2 * G3;

    const int b    = blockIdx.x;
    const int tid  = threadIdx.x;
    const int row  = tid % G3;
    const int half = tid / G3;

    for (int i4 = tid; i4 < TT * G3 / 4; i4 += 384)
        ((float4*)gi)[i4] = ((const float4*)(g_gi0 + (size_t)b * TT * G3))[i4];
    for (int i4 = tid; i4 < G3 * 16; i4 += 384) {
        int r = i4 >> 4, c4 = i4 & 15;
        *(float4*)(Whs0 + r * WS + 4 * c4) = ld4g(Whh0 + r * GRUH + 4 * c4);
        *(float4*)(Whs1 + r * WS + 4 * c4) = ld4g(Whh1 + r * GRUH + 4 * c4);
        *(float4*)(Wis1 + r * WS + 4 * c4) = ld4g(Wih1 + r * GRUH + 4 * c4);
    }
    if (tid < GRUH) hbuf[tid] = 0.f;
    __syncthreads();

    float wr[32];
    {
        const float* wrow = Whs0 + row * WS + half * 32;
        #pragma unroll
        for (int i = 0; i < 8; i++) {
            float4 v = ld4(wrow + 4 * i);
            wr[4*i] = v.x; wr[4*i+1] = v.y; wr[4*i+2] = v.z; wr[4*i+3] = v.w;
        }
    }
    float bh = (half == 0) ? __ldg(bhh0 + row) : 0.f;
    __syncthreads();

    for (int t = 0; t < TT; t++) {
        const float* hb = hbuf + half * 32;
        float acc[4] = {0.f, 0.f, 0.f, 0.f};
        #pragma unroll
        for (int j = 0; j < 4; j++) {
            float4 ha = ld4(hb + 8 * j);
            float4 hc = ld4(hb + 8 * j + 4);
            acc[j] += wr[8*j  ]*ha.x + wr[8*j+1]*ha.y + wr[8*j+2]*ha.z + wr[8*j+3]*ha.w
                    + wr[8*j+4]*hc.x + wr[8*j+5]*hc.y + wr[8*j+6]*hc.z + wr[8*j+7]*hc.w;
        }
        ghp[half * G3 + row] = (acc[0] + acc[1]) + (acc[2] + acc[3]) + bh;
        __syncthreads();
        if (tid < GRUH) {
            float ghr = ghp[tid]       + ghp[G3 + tid];
            float ghz = ghp[64 + tid]  + ghp[G3 + 64 + tid];
            float ghn = ghp[128 + tid] + ghp[G3 + 128 + tid];
            float r = fast_sigmoid(gi[t * G3 + tid] + ghr);
            float z = fast_sigmoid(gi[t * G3 + GRUH + tid] + ghz);
            float n = fast_tanh(gi[t * G3 + 2 * GRUH + tid] + r * ghn);
            float hn = (1.f - z) * n + z * hbuf[tid];
            hbuf[tid] = hn;
            seq[t * GRUH + tid] = hn;
        }
        __syncthreads();
    }

    {
        float acc8[8];
        float bi = __ldg(bih1 + row);
        #pragma unroll
        for (int t = 0; t < 8; t++) acc8[t] = bi;
        const float* wrow = Wis1 + row * WS;
        const int t0 = half * 8;
        #pragma unroll
        for (int f4 = 0; f4 < 16; f4++) {
            float4 w = ld4(wrow + 4 * f4);
            #pragma unroll
            for (int t = 0; t < 8; t++) {
                float4 xv = ld4(seq + (t0 + t) * GRUH + 4 * f4);
                acc8[t] += w.x * xv.x + w.y * xv.y + w.z * xv.z + w.w * xv.w;
            }
        }
        #pragma unroll
        for (int t = 0; t < 8; t++) gi[(t0 + t) * G3 + row] = acc8[t];
    }

    {
        const float* wrow = Whs1 + row * WS + half * 32;
        #pragma unroll
        for (int i = 0; i < 8; i++) {
            float4 v = ld4(wrow + 4 * i);
            wr[4*i] = v.x; wr[4*i+1] = v.y; wr[4*i+2] = v.z; wr[4*i+3] = v.w;
        }
    }
    bh = (half == 0) ? __ldg(bhh1 + row) : 0.f;
    if (tid < GRUH) hbuf[tid] = 0.f;
    __syncthreads();

    for (int t = 0; t < TT; t++) {
        const float* hb = hbuf + half * 32;
        float acc[4] = {0.f, 0.f, 0.f, 0.f};
        #pragma unroll
        for (int j = 0; j < 4; j++) {
            float4 ha = ld4(hb + 8 * j);
            float4 hc = ld4(hb + 8 * j + 4);
            acc[j] += wr[8*j  ]*ha.x + wr[8*j+1]*ha.y + wr[8*j+2]*ha.z + wr[8*j+3]*ha.w
                    + wr[8*j+4]*hc.x + wr[8*j+5]*hc.y + wr[8*j+6]*hc.z + wr[8*j+7]*hc.w;
        }
        ghp[half * G3 + row] = (acc[0] + acc[1]) + (acc[2] + acc[3]) + bh;
        __syncthreads();
        if (tid < GRUH) {
            float ghr = ghp[tid]       + ghp[G3 + tid];
            float ghz = ghp[64 + tid]  + ghp[G3 + 64 + tid];
            float ghn = ghp[128 + tid] + ghp[G3 + 128 + tid];
            float r = fast_sigmoid(gi[t * G3 + tid] + ghr);
            float z = fast_sigmoid(gi[t * G3 + GRUH + tid] + ghz);
            float n = fast_tanh(gi[t * G3 + 2 * GRUH + tid] + r * ghn);
            hbuf[tid] = (1.f - z) * n + z * hbuf[tid];
        }
        __syncthreads();
    }

    if (tid < 32) {
        float acc = __ldg(bh1 + tid);
        #pragma unroll
        for (int u = 0; u < GRUH; u++) acc += hbuf[u] * __ldg(Wh1 + u * 32 + tid);
        q[tid] = fmaxf(acc, 0.f);
    }
    __syncthreads();
    if (tid == 0) {
        float acc = __ldg(bh2);
        #pragma unroll
        for (int m = 0; m < 32; m++) acc += q[m] * __ldg(Wh2 + m);
        out[b] = acc;
    }
}

// ---------------------------------------------------------------------------
extern "C" void kernel_launch(void* const* d_in, const int* in_sizes, int n_in,
                              void* d_out, int out_size)
{
    const float* x    = (const float*)d_in[0];
    const float* W1   = (const float*)d_in[3];
    const float* as1  = (const float*)d_in[4];
    const float* ad1  = (const float*)d_in[5];
    const float* b1   = (const float*)d_in[6];
    const float* W2   = (const float*)d_in[7];
    const float* as2  = (const float*)d_in[8];
    const float* ad2  = (const float*)d_in[9];
    const float* b2   = (const float*)d_in[10];
    const float* Wih0 = (const float*)d_in[11];
    const float* Whh0 = (const float*)d_in[12];
    const float* bih0 = (const float*)d_in[13];
    const float* bhh0 = (const float*)d_in[14];
    const float* Wih1 = (const float*)d_in[15];
    const float* Whh1 = (const float*)d_in[16];
    const float* bih1 = (const float*)d_in[17];
    const float* bhh1 = (const float*)d_in[18];
    const float* Wh1  = (const float*)d_in[19];
    const float* bh1  = (const float*)d_in[20];
    const float* Wh2  = (const float*)d_in[21];
    const float* bh2  = (const float*)d_in[22];

    const int GAT_SMEM = 11416 * 4;   // 45664 B -> 4 blocks/SM
    const int GI0_SMEM = (G3 * 100 + GI0_GPB * FRAME) * 4;
    const int GRU_SMEM = 43744 * 4;

    static bool attrs_set = false;
    if (!attrs_set) {
        cudaFuncSetAttribute(gat_kernel, cudaFuncAttributeMaxDynamicSharedMemorySize, GAT_SMEM);
        cudaFuncSetAttribute(gi0_kernel, cudaFuncAttributeMaxDynamicSharedMemorySize, GI0_SMEM);
        cudaFuncSetAttribute(gru_kernel, cudaFuncAttributeMaxDynamicSharedMemorySize, GRU_SMEM);
        attrs_set = true;
    }

    gat_kernel<<<NGRAPH, 256, GAT_SMEM>>>(x, W1, as1, ad1, b1, W2, as2, ad2, b2);
    gi0_kernel<<<NGRAPH / GI0_GPB, 192, GI0_SMEM>>>(Wih0, bih0);
    gru_kernel<<<BB, 384, GRU_SMEM>>>(Whh0, bhh0, Wih1, bih1, Whh1, bhh1,
                                      Wh1, bh1, Wh2, bh2, (float*)d_out);
}